// round 9
// baseline (speedup 1.0000x reference)
#include <cuda_runtime.h>
#include <cuda_bf16.h>
#include <cuda_fp16.h>
#include <cuda_fp8.h>

// Problem dims
#define M_TOK 8192     // B*S
#define K_FEAT 2048    // FEATURES
#define N_HID 8192     // HIDDEN

// Tiling
#define BM 128
#define BN 64
#define BK 32
#define NTHREADS 256   // 8 warps: 4 (m) x 2 (n), warp tile 32x32

#include <mma.h>
using namespace nvcuda;

// ---------------- device scratch ----------------
__device__ __half g_xh[(size_t)M_TOK * K_FEAT];   // e4m3(x) as half
__device__ __half g_w0[(size_t)K_FEAT * N_HID];   // e4m3(w_gating[0]) as half
__device__ __half g_w1[(size_t)K_FEAT * N_HID];   // e4m3(w_gating[1]) as half
__device__ __half g_wl[(size_t)N_HID * K_FEAT];   // e4m3(w_linear) as half
__device__ __half g_act[(size_t)M_TOK * N_HID];   // e4m3(gelu(g)*f) as half

__device__ int g_sel;  // 1 if candA is x, 0 if candB is x

__device__ __forceinline__ __half q_e4m3_h(float v) {
    __nv_fp8_storage_t q = __nv_cvt_float_to_fp8(v, __NV_SATFINITE, __NV_E4M3);
    return __half(__nv_cvt_fp8_to_halfraw(q, __NV_E4M3));
}
__device__ __forceinline__ float bf16r(float v) {
    return __bfloat162float(__float2bfloat16(v));
}

// ---------------- discriminator (both candidates fp32) ----------------
// x ~ N(0,1): max|.| over 4096 ~ 3.5 ; w_linear std 0.011: max ~ 0.05.
__global__ void discrim_kernel(const float* __restrict__ candA,
                               const float* __restrict__ candB) {
    __shared__ float smA[256], smB[256];
    int tid = threadIdx.x;
    float ma = 0.0f, mb = 0.0f;
    for (int i = tid; i < 4096; i += 256) {
        float a = fabsf(candA[i]);
        float b = fabsf(candB[i]);
        if (isfinite(a)) ma = fmaxf(ma, a);
        if (isfinite(b)) mb = fmaxf(mb, b);
    }
    smA[tid] = ma; smB[tid] = mb;
    __syncthreads();
    for (int s = 128; s > 0; s >>= 1) {
        if (tid < s) {
            smA[tid] = fmaxf(smA[tid], smA[tid + s]);
            smB[tid] = fmaxf(smB[tid], smB[tid + s]);
        }
        __syncthreads();
    }
    if (tid == 0) g_sel = (smA[0] > smB[0]) ? 1 : 0;
}

// ---------------- quantization (ALL inputs fp32) ----------------
__global__ void quant_x_kernel(const float* __restrict__ candA,
                               const float* __restrict__ candB) {
    const float* x = g_sel ? candA : candB;
    size_t i = (size_t)blockIdx.x * blockDim.x + threadIdx.x;
    if (i < (size_t)M_TOK * K_FEAT) g_xh[i] = q_e4m3_h(x[i]);
}
__global__ void quant_wl_kernel(const float* __restrict__ candA,
                                const float* __restrict__ candB) {
    const float* w = g_sel ? candB : candA;
    size_t i = (size_t)blockIdx.x * blockDim.x + threadIdx.x;
    if (i < (size_t)N_HID * K_FEAT) g_wl[i] = q_e4m3_h(w[i]);
}
__global__ void quant_wg_kernel(const float* __restrict__ w) {
    size_t i = (size_t)blockIdx.x * blockDim.x + threadIdx.x;
    size_t n = (size_t)K_FEAT * N_HID;
    if (i < n) {
        g_w0[i] = q_e4m3_h(w[i]);
        g_w1[i] = q_e4m3_h(w[i + n]);
    }
}

// ---------------- GEMM1 (WMMA, fused gate+ff1 -> GeGLU -> e4m3 act) ----------
__global__ __launch_bounds__(NTHREADS) void gemm1_kernel() {
    __shared__ __half As[BM][BK + 8];
    __shared__ __half Bs0[BK][BN + 8];
    __shared__ __half Bs1[BK][BN + 8];
    __shared__ float stage[8][2][16][20];  // ldm=20 floats = 80B (multiple of 16B: OK)

    const int tid  = threadIdx.x;
    const int warp = tid >> 5;
    const int lane = tid & 31;
    const int wm = warp >> 1;   // 0..3
    const int wn = warp & 1;    // 0..1
    const int m0 = blockIdx.y * BM;
    const int n0 = blockIdx.x * BN;

    wmma::fragment<wmma::accumulator, 16, 16, 16, float> acc0[2][2], acc1[2][2];
    #pragma unroll
    for (int i = 0; i < 2; i++)
        #pragma unroll
        for (int j = 0; j < 2; j++) {
            wmma::fill_fragment(acc0[i][j], 0.0f);
            wmma::fill_fragment(acc1[i][j], 0.0f);
        }

    for (int kt = 0; kt < K_FEAT; kt += BK) {
        #pragma unroll
        for (int t = 0; t < 2; t++) {
            int idx = tid + t * NTHREADS;
            int r = idx >> 2, cv = idx & 3;
            uint4 v = *reinterpret_cast<const uint4*>(
                &g_xh[(size_t)(m0 + r) * K_FEAT + kt + cv * 8]);
            *reinterpret_cast<uint4*>(&As[r][cv * 8]) = v;
        }
        {
            int r = tid >> 3, cv = tid & 7;
            *reinterpret_cast<uint4*>(&Bs0[r][cv * 8]) =
                *reinterpret_cast<const uint4*>(&g_w0[(size_t)(kt + r) * N_HID + n0 + cv * 8]);
            *reinterpret_cast<uint4*>(&Bs1[r][cv * 8]) =
                *reinterpret_cast<const uint4*>(&g_w1[(size_t)(kt + r) * N_HID + n0 + cv * 8]);
        }
        __syncthreads();

        #pragma unroll
        for (int kk = 0; kk < BK; kk += 16) {
            wmma::fragment<wmma::matrix_a, 16, 16, 16, __half, wmma::row_major> af[2];
            wmma::fragment<wmma::matrix_b, 16, 16, 16, __half, wmma::row_major> bf0[2], bf1[2];
            #pragma unroll
            for (int i = 0; i < 2; i++)
                wmma::load_matrix_sync(af[i], &As[wm * 32 + i * 16][kk], BK + 8);
            #pragma unroll
            for (int j = 0; j < 2; j++) {
                wmma::load_matrix_sync(bf0[j], &Bs0[kk][wn * 32 + j * 16], BN + 8);
                wmma::load_matrix_sync(bf1[j], &Bs1[kk][wn * 32 + j * 16], BN + 8);
            }
            #pragma unroll
            for (int i = 0; i < 2; i++)
                #pragma unroll
                for (int j = 0; j < 2; j++) {
                    wmma::mma_sync(acc0[i][j], af[i], bf0[j], acc0[i][j]);
                    wmma::mma_sync(acc1[i][j], af[i], bf1[j], acc1[i][j]);
                }
        }
        __syncthreads();
    }

    // Epilogue: per-op bf16-rounded GeGLU chain (matches jax.nn.gelu on bf16).
    const float C1 = 0.044677734375f;  // bf16(0.044715)
    const float C2 = 0.796875f;        // bf16(sqrt(2/pi))
    #pragma unroll
    for (int i = 0; i < 2; i++) {
        #pragma unroll
        for (int j = 0; j < 2; j++) {
            wmma::store_matrix_sync(&stage[warp][0][0][0], acc0[i][j], 20, wmma::mem_row_major);
            wmma::store_matrix_sync(&stage[warp][1][0][0], acc1[i][j], 20, wmma::mem_row_major);
            __syncwarp();
            #pragma unroll
            for (int e = 0; e < 8; e++) {
                int idx = lane * 8 + e;
                int r = idx >> 4, c = idx & 15;
                float gb = bf16r(stage[warp][0][r][c]);   // ff_gate (bf16)
                float fb = bf16r(stage[warp][1][r][c]);   // ff1 (bf16)
                float t1 = bf16r(gb * gb);
                float t2 = bf16r(t1 * gb);
                float t3 = bf16r(C1 * t2);
                float t4 = bf16r(gb + t3);
                float t5 = bf16r(C2 * t4);
                float t6 = bf16r(tanhf(t5));
                float t7 = bf16r(t6 + 1.0f);
                float t8 = 0.5f * t7;
                float gl = bf16r(gb * t8);
                float pr = bf16r(gl * fb);
                size_t row = (size_t)(m0 + wm * 32 + i * 16 + r);
                size_t col = (size_t)(n0 + wn * 32 + j * 16 + c);
                g_act[row * N_HID + col] = q_e4m3_h(pr);
            }
            __syncwarp();
        }
    }
}

// ---------------- GEMM2 (WMMA): act @ w_linear -> fp32 out (bf16-rounded) ----
__global__ __launch_bounds__(NTHREADS) void gemm2_kernel(float* __restrict__ out) {
    __shared__ __half As[BM][BK + 8];
    __shared__ __half Bs[BK][BN + 8];
    __shared__ float stage[8][16][20];  // ldm=20: valid

    const int tid  = threadIdx.x;
    const int warp = tid >> 5;
    const int lane = tid & 31;
    const int wm = warp >> 1;
    const int wn = warp & 1;
    const int m0 = blockIdx.y * BM;
    const int n0 = blockIdx.x * BN;

    wmma::fragment<wmma::accumulator, 16, 16, 16, float> acc[2][2];
    #pragma unroll
    for (int i = 0; i < 2; i++)
        #pragma unroll
        for (int j = 0; j < 2; j++)
            wmma::fill_fragment(acc[i][j], 0.0f);

    for (int kt = 0; kt < N_HID; kt += BK) {
        #pragma unroll
        for (int t = 0; t < 2; t++) {
            int idx = tid + t * NTHREADS;
            int r = idx >> 2, cv = idx & 3;
            uint4 v = *reinterpret_cast<const uint4*>(
                &g_act[(size_t)(m0 + r) * N_HID + kt + cv * 8]);
            *reinterpret_cast<uint4*>(&As[r][cv * 8]) = v;
        }
        {
            int r = tid >> 3, cv = tid & 7;
            *reinterpret_cast<uint4*>(&Bs[r][cv * 8]) =
                *reinterpret_cast<const uint4*>(&g_wl[(size_t)(kt + r) * K_FEAT + n0 + cv * 8]);
        }
        __syncthreads();

        #pragma unroll
        for (int kk = 0; kk < BK; kk += 16) {
            wmma::fragment<wmma::matrix_a, 16, 16, 16, __half, wmma::row_major> af[2];
            wmma::fragment<wmma::matrix_b, 16, 16, 16, __half, wmma::row_major> bf[2];
            #pragma unroll
            for (int i = 0; i < 2; i++)
                wmma::load_matrix_sync(af[i], &As[wm * 32 + i * 16][kk], BK + 8);
            #pragma unroll
            for (int j = 0; j < 2; j++)
                wmma::load_matrix_sync(bf[j], &Bs[kk][wn * 32 + j * 16], BN + 8);
            #pragma unroll
            for (int i = 0; i < 2; i++)
                #pragma unroll
                for (int j = 0; j < 2; j++)
                    wmma::mma_sync(acc[i][j], af[i], bf[j], acc[i][j]);
        }
        __syncthreads();
    }

    #pragma unroll
    for (int i = 0; i < 2; i++) {
        #pragma unroll
        for (int j = 0; j < 2; j++) {
            wmma::store_matrix_sync(&stage[warp][0][0], acc[i][j], 20, wmma::mem_row_major);
            __syncwarp();
            #pragma unroll
            for (int e = 0; e < 8; e++) {
                int idx = lane * 8 + e;
                int r = idx >> 4, c = idx & 15;
                // Reference output is bf16; harness stores it upcast to fp32.
                float v = bf16r(stage[warp][r][c]);
                size_t row = (size_t)(m0 + wm * 32 + i * 16 + r);
                size_t col = (size_t)(n0 + wn * 32 + j * 16 + c);
                out[row * K_FEAT + col] = v;
            }
            __syncwarp();
        }
    }
}

// ---------------- launch ----------------
extern "C" void kernel_launch(void* const* d_in, const int* in_sizes, int n_in,
                              void* d_out, int out_size) {
    const size_t WG_N = (size_t)2 * K_FEAT * N_HID;  // 33554432 — unique to w_gating
    int wg_i = 1;
    for (int i = 0; i < n_in && i < 3; i++) {
        if ((size_t)in_sizes[i] == WG_N) { wg_i = i; break; }
    }
    int others[2]; int c = 0;
    for (int i = 0; i < 3; i++) if (i != wg_i) others[c++] = i;

    const float* wg    = (const float*)d_in[wg_i];
    const float* candA = (const float*)d_in[others[0]];
    const float* candB = (const float*)d_in[others[1]];
    float*       out   = (float*)d_out;   // fp32 output buffer

    discrim_kernel<<<1, 256>>>(candA, candB);

    {
        size_t n = (size_t)M_TOK * K_FEAT;
        quant_x_kernel<<<(unsigned)((n + 255) / 256), 256>>>(candA, candB);
    }
    {
        size_t n = (size_t)K_FEAT * N_HID;
        quant_wg_kernel<<<(unsigned)((n + 255) / 256), 256>>>(wg);
    }
    {
        size_t n = (size_t)N_HID * K_FEAT;
        quant_wl_kernel<<<(unsigned)((n + 255) / 256), 256>>>(candA, candB);
    }

    dim3 g1(N_HID / BN, M_TOK / BM);   // (128, 64)
    gemm1_kernel<<<g1, NTHREADS>>>();

    dim3 g2(K_FEAT / BN, M_TOK / BM); // (32, 64)
    gemm2_kernel<<<g2, NTHREADS>>>(out);
}